// round 10
// baseline (speedup 1.0000x reference)
#include <cuda_runtime.h>
#include <cuda_fp16.h>
#include <cstdint>

// KPConv, GB300 (sm_103a; harness compiles at compute_103 -> no tcgen05).
// Round 10: software-pipelined aggregation (double-buffered cp.async batches).
// While batch k runs weight+FMA, batch k+1's nbr load + point/feature copies
// are in flight. Per-warp work-item stream over its 4 rows; acc flushed to
// the SMEM A tile at row boundaries. GEMM phase = validated R9 scheme.

#define KP       15
#define FDIM     32
#define CDIM     64
#define KK       480
#define BM       32
#define THREADS  256
#define NSTEP    30
#define INV_EXTENT (1.0f / 0.6f)

#define ROW_STRIDE 976                    // 480 fp16 = 960B + 16B pad
#define A_BYTES    (BM * ROW_STRIDE)      // 31232
#define BUF_BYTES  2304                   // ftile 2048 + ptile 256
#define BUFS_OFF   A_BYTES                // per warp: 2 bufs
#define BUFS_BYTES (8 * 2 * BUF_BYTES)    // 36864
#define SMEM_BYTES (BUFS_OFF + BUFS_BYTES)   // 68096 dynamic

__device__ uint4  g_bfrag[4 * NSTEP * 32];
__device__ int    g_rowptr[40001];

typedef unsigned long long ull;

__device__ __forceinline__ ull pack2f(float lo, float hi) {
    ull d; asm("mov.b64 %0, {%1, %2};" : "=l"(d) : "f"(lo), "f"(hi)); return d;
}
__device__ __forceinline__ void unpack2f(ull s, float& lo, float& hi) {
    asm("mov.b64 {%0, %1}, %2;" : "=f"(lo), "=f"(hi) : "l"(s));
}
__device__ __forceinline__ ull ffma2(ull a, ull b, ull c) {
    ull d; asm("fma.rn.f32x2 %0, %1, %2, %3;" : "=l"(d) : "l"(a), "l"(b), "l"(c)); return d;
}
__device__ __forceinline__ uint32_t smem_u32(const void* p) {
    uint32_t a;
    asm("{ .reg .u64 t; cvta.to.shared.u64 t, %1; cvt.u32.u64 %0, t; }" : "=r"(a) : "l"(p));
    return a;
}
__device__ __forceinline__ void ldsm4(uint32_t addr, uint32_t* r) {
    asm volatile("ldmatrix.sync.aligned.m8n8.x4.shared.b16 {%0,%1,%2,%3}, [%4];"
                 : "=r"(r[0]), "=r"(r[1]), "=r"(r[2]), "=r"(r[3]) : "r"(addr));
}
__device__ __forceinline__ void mma16816h(float* d, const uint32_t* a,
                                          uint32_t b0, uint32_t b1) {
    asm volatile(
        "mma.sync.aligned.m16n8k16.row.col.f32.f16.f16.f32 "
        "{%0,%1,%2,%3}, {%4,%5,%6,%7}, {%8,%9}, {%0,%1,%2,%3};"
        : "+f"(d[0]), "+f"(d[1]), "+f"(d[2]), "+f"(d[3])
        : "r"(a[0]), "r"(a[1]), "r"(a[2]), "r"(a[3]), "r"(b0), "r"(b1));
}
__device__ __forceinline__ void cpa4(uint32_t dst, const void* src) {
    asm volatile("cp.async.ca.shared.global [%0], [%1], 4;" :: "r"(dst), "l"(src));
}
__device__ __forceinline__ void cpa16(uint32_t dst, const void* src) {
    asm volatile("cp.async.ca.shared.global [%0], [%1], 16;" :: "r"(dst), "l"(src));
}

// ================= prep: bfrag + rowptr =================
__global__ void prep_kernel(const float* __restrict__ kv,
                            const int* __restrict__ sid, int E, int M) {
    int b = blockIdx.x;
    int t = threadIdx.x;
    if (b == 0) {
        for (int i = t; i < 4 * NSTEP * 32; i += 256) {
            int l  = i & 31;
            int s  = (i >> 5) % NSTEP;
            int wn = i / (NSTEP * 32);
            int n0 = wn * 16 + (l >> 2);
            int kb = s * 16 + 2 * (l & 3);
            auto h2 = [&](int n, int k) -> uint32_t {
                __half2 p = __halves2half2(__float2half_rn(kv[k * CDIM + n]),
                                           __float2half_rn(kv[(k + 1) * CDIM + n]));
                return *(uint32_t*)&p;
            };
            uint4 v;
            v.x = h2(n0,     kb);
            v.y = h2(n0 + 8, kb);
            v.z = h2(n0,     kb + 8);
            v.w = h2(n0 + 8, kb + 8);
            g_bfrag[i] = v;
        }
    } else {
        int i = (b - 1) * 256 + t;
        if (i >= E) return;
        int s  = __ldg(sid + i);
        int sp = (i == 0) ? -1 : __ldg(sid + i - 1);
        for (int m = sp + 1; m <= s; m++) g_rowptr[m] = i;
        if (i == E - 1)
            for (int m = s + 1; m <= M; m++) g_rowptr[m] = E;
    }
}

// ================= main: pipelined fused agg + GEMM =================
__global__ __launch_bounds__(THREADS, 3) void kpconv_main_kernel(
    const float* __restrict__ points,
    const float* __restrict__ features,
    const float* __restrict__ outp,
    const int*   __restrict__ nbr,
    const float* __restrict__ kpts,
    float*       __restrict__ out,
    int M)
{
    extern __shared__ __align__(128) char sm[];    // A tile + double buffers
    __shared__ ull   w2_s[8 * 8 * 16];             // [warp][pair][edge]
    __shared__ float kp[KP * 3];

    const uint32_t sbase = smem_u32(sm);
    const int tid  = threadIdx.x;
    const int warp = tid >> 5;
    const int lane = tid & 31;
    const int m0   = blockIdx.x * BM;

    if (tid < KP * 3) kp[tid] = kpts[tid];

    // zero this warp's 4 A-tile rows (empty rows must read as 0 in GEMM)
    {
        uint4 zz = make_uint4(0, 0, 0, 0);
        #pragma unroll
        for (int rr = 0; rr < 4; rr++) {
            uint4* ar = (uint4*)(sm + (warp + 8 * rr) * ROW_STRIDE);
            for (int i = lane; i < ROW_STRIDE / 16; i += 32) ar[i] = zz;
        }
    }
    __syncthreads();

    // per-warp row metadata
    int s4[4], e4[4];
    float ox[4], oy[4], oz[4];
    #pragma unroll
    for (int rr = 0; rr < 4; rr++) {
        int m = m0 + warp + 8 * rr;
        if (m < M) {
            s4[rr] = __ldg(g_rowptr + m);
            e4[rr] = __ldg(g_rowptr + m + 1);
            ox[rr] = __ldg(outp + m * 3 + 0);
            oy[rr] = __ldg(outp + m * 3 + 1);
            oz[rr] = __ldg(outp + m * 3 + 2);
        } else { s4[rr] = 0; e4[rr] = 0; ox[rr] = oy[rr] = oz[rr] = 0.f; }
    }

    ull* wrow = w2_s + warp * 128;
    const uint32_t bufs_a = sbase + BUFS_OFF + warp * (2 * BUF_BYTES);

    auto prefetch = [&](int rrP, int baseP, int buf) {
        int cnt = e4[rrP] - baseP; if (cnt > 16) cnt = 16;
        int my_ni = 0;
        if (lane < cnt) my_ni = __ldg(nbr + baseP + lane);
        uint32_t wb = bufs_a + buf * BUF_BYTES;
        #pragma unroll
        for (int q = 0; q < 2; q++) {                 // points: 16 edges x 3 x 4B
            int t2 = q * 32 + lane;
            int edge = t2 >> 2, comp = t2 & 3;
            int ni = __shfl_sync(0xffffffffu, my_ni, edge);   // uniform shfl
            if (edge < cnt && comp < 3)
                cpa4(wb + 2048 + (edge * 4 + comp) * 4,
                     points + (size_t)ni * 3 + comp);
        }
        #pragma unroll
        for (int q = 0; q < 4; q++) {                 // features: 16 edges x 128B
            int t2 = q * 32 + lane;
            int edge = t2 >> 3, chunk = t2 & 7;
            int ni = __shfl_sync(0xffffffffu, my_ni, edge);   // uniform shfl
            if (edge < cnt)
                cpa16(wb + (edge * 32 + chunk * 4) * 4,
                      features + (size_t)ni * FDIM + chunk * 4);
        }
        asm volatile("cp.async.commit_group;");
    };

    ull acc2[8];
    #pragma unroll
    for (int p = 0; p < 8; p++) acc2[p] = 0ull;

    auto consume = [&](int rrC, int baseC, int buf) {
        int cnt = e4[rrC] - baseC; if (cnt > 16) cnt = 16;
        char* fb = sm + BUFS_OFF + warp * (2 * BUF_BYTES) + buf * BUF_BYTES;
        float* ftile = (float*)fb;
        float* ptile = (float*)(fb + 2048);

        if (lane < 16) {                              // weight phase: lane = edge
            float rx = ptile[lane * 4 + 0] - ox[rrC];
            float ry = ptile[lane * 4 + 1] - oy[rrC];
            float rz = ptile[lane * 4 + 2] - oz[rrC];
            #pragma unroll
            for (int p = 0; p < 8; p++) {
                float w0, w1 = 0.f;
                {
                    int k = 2 * p;
                    float dx = rx - kp[k * 3 + 0];
                    float dy = ry - kp[k * 3 + 1];
                    float dz = rz - kp[k * 3 + 2];
                    float sq = fmaf(dx, dx, fmaf(dy, dy, dz * dz));
                    w0 = fmaxf(1.f - sqrtf(sq) * INV_EXTENT, 0.f);
                }
                if (p < 7) {
                    int k = 2 * p + 1;
                    float dx = rx - kp[k * 3 + 0];
                    float dy = ry - kp[k * 3 + 1];
                    float dz = rz - kp[k * 3 + 2];
                    float sq = fmaf(dx, dx, fmaf(dy, dy, dz * dz));
                    w1 = fmaxf(1.f - sqrtf(sq) * INV_EXTENT, 0.f);
                }
                wrow[p * 16 + lane] = pack2f(w0, w1);
            }
        }
        __syncwarp();

        for (int j = 0; j < cnt; ++j) {               // FMA phase: lane = channel
            float ft = ftile[j * 32 + lane];
            ull fd = pack2f(ft, ft);
            #pragma unroll
            for (int p = 0; p < 8; p++)
                acc2[p] = ffma2(fd, wrow[p * 16 + j], acc2[p]);
        }
        __syncwarp();

        if (baseC + 16 >= e4[rrC]) {                  // last batch of row: flush
            char* ar = sm + (warp + 8 * rrC) * ROW_STRIDE;
            #pragma unroll
            for (int p = 0; p < 8; p++) {
                float v0, v1;
                unpack2f(acc2[p], v0, v1);
                int k0 = (2 * p) * 32 + lane;
                *(__half*)(ar + k0 * 2) = __float2half_rn(v0);
                if (p < 7) {
                    int k1 = (2 * p + 1) * 32 + lane;
                    *(__half*)(ar + k1 * 2) = __float2half_rn(v1);
                }
                acc2[p] = 0ull;
            }
        }
    };

    // ---- pipelined batch loop ----
    int rr = 0;
    while (rr < 4 && s4[rr] >= e4[rr]) rr++;
    int base = (rr < 4) ? s4[rr] : 0;
    int buf = 0;
    if (rr < 4) prefetch(rr, base, 0);

    while (rr < 4) {
        int nrr = rr, nbase = base + 16;
        if (nbase >= e4[nrr]) {
            nrr++;
            while (nrr < 4 && s4[nrr] >= e4[nrr]) nrr++;
            nbase = (nrr < 4) ? s4[nrr] : 0;
        }
        bool hn = (nrr < 4);
        if (hn) {
            prefetch(nrr, nbase, buf ^ 1);
            asm volatile("cp.async.wait_group 1;");
        } else {
            asm volatile("cp.async.wait_group 0;");
        }
        __syncwarp();
        consume(rr, base, buf);
        rr = nrr; base = nbase; buf ^= 1;
    }
    __syncthreads();

    // ---------------- Phase B: GEMM [32,480] x [64,480]^T ----------------
    const int warp_m = warp & 1;
    const int warp_n = warp >> 1;
    const uint32_t abase = sbase + (uint32_t)(warp_m * 16 + (lane & 15)) * ROW_STRIDE
                         + (uint32_t)(lane >> 4) * 16;
    const uint4* bf = g_bfrag + (size_t)warp_n * NSTEP * 32 + lane;

    float acc[2][4];
    #pragma unroll
    for (int nt = 0; nt < 2; nt++)
        #pragma unroll
        for (int i = 0; i < 4; i++) acc[nt][i] = 0.f;

    #pragma unroll
    for (int s = 0; s < NSTEP; s++) {
        uint32_t a[4];
        ldsm4(abase + (uint32_t)s * 32, a);
        uint4 f = __ldg(bf + s * 32);
        mma16816h(acc[0], a, f.x, f.z);
        mma16816h(acc[1], a, f.y, f.w);
    }

    const int qr = lane >> 2;
    const int qc = (lane & 3) * 2;
    #pragma unroll
    for (int nt = 0; nt < 2; nt++) {
        int r0 = m0 + warp_m * 16 + qr;
        int cc = warp_n * 16 + nt * 8 + qc;
        if (r0 < M)
            *(float2*)(out + (size_t)r0 * CDIM + cc) = make_float2(acc[nt][0], acc[nt][1]);
        if (r0 + 8 < M)
            *(float2*)(out + (size_t)(r0 + 8) * CDIM + cc) = make_float2(acc[nt][2], acc[nt][3]);
    }
}

// ================= launch =================
extern "C" void kernel_launch(void* const* d_in, const int* in_sizes, int n_in,
                              void* d_out, int out_size) {
    const float* points   = (const float*)d_in[0];
    const float* features = (const float*)d_in[1];
    const float* outp     = (const float*)d_in[2];
    const int*   nbr      = (const int*)d_in[3];
    const int*   sid      = (const int*)d_in[4];
    const float* kpts     = (const float*)d_in[5];
    const float* kv       = (const float*)d_in[6];
    float*       out      = (float*)d_out;

    int E = in_sizes[3];
    int M = out_size / CDIM;

    static bool attr_set = false;
    if (!attr_set) {
        cudaFuncSetAttribute(kpconv_main_kernel,
                             cudaFuncAttributeMaxDynamicSharedMemorySize,
                             SMEM_BYTES);
        attr_set = true;
    }

    int prep_blocks = 1 + (E + 255) / 256;
    prep_kernel<<<prep_blocks, 256>>>(kv, sid, E, M);
    int blocks = (M + BM - 1) / BM;
    kpconv_main_kernel<<<blocks, THREADS, SMEM_BYTES>>>(
        points, features, outp, nbr, kpts, out, M);
}